// round 17
// baseline (speedup 1.0000x reference)
#include <cuda_runtime.h>
#include <cuda_bf16.h>

// Problem constants (fixed by the reference):
//   N=100000 nodes, E=1600000 edges, IN=128, HID=64, OUT=8, B=16384
// NOTE: reference uses jnp.int64 but JAX x64 is disabled -> edge_index/idx are int32.
#define N_MAX 100000
#define E_MAX 1600000

// ---------------- scratch (device globals; no allocation allowed) ----------
__device__ __align__(256) int   g_deg[N_MAX];
__device__ __align__(256) int   g_rowstart[N_MAX + 1];
__device__ __align__(256) int   g_cursor[N_MAX];
__device__ __align__(256) int   g_srclist[E_MAX];
__device__ __align__(256) int   g_blocksums[512];
__device__ __align__(256) float g_y[(size_t)N_MAX * 128];  // [N][0:64)=x@W1_l, [64:128)=x@W1_r
__device__ __align__(256) float g_h[(size_t)N_MAX * 64];   // layer-1 activations
__device__ __align__(256) float g_z[(size_t)N_MAX * 8];    // h @ W2_l

// ---------------- bf16 split helpers ----------------------------------------
// a = hi + lo + r, |r| ~ 2^-17 |a|. bf16x3 mma drops lo*lo (~2^-18) + r terms.
__device__ __forceinline__ void bsplit(float a, unsigned short& h, unsigned short& l) {
    __nv_bfloat16 hb = __float2bfloat16(a);
    __nv_bfloat16 lb = __float2bfloat16(a - __bfloat162float(hb));
    h = __bfloat16_as_ushort(hb);
    l = __bfloat16_as_ushort(lb);
}
__device__ __forceinline__ unsigned pk(unsigned short lo16, unsigned short hi16) {
    return (unsigned)lo16 | ((unsigned)hi16 << 16);  // low bits = lower-k element
}
__device__ __forceinline__ void mma_bf16(float c[4],
                                         unsigned a0, unsigned a1, unsigned a2, unsigned a3,
                                         unsigned b0, unsigned b1) {
    asm volatile(
        "mma.sync.aligned.m16n8k16.row.col.f32.bf16.bf16.f32 "
        "{%0,%1,%2,%3}, {%4,%5,%6,%7}, {%8,%9}, {%0,%1,%2,%3};"
        : "+f"(c[0]), "+f"(c[1]), "+f"(c[2]), "+f"(c[3])
        : "r"(a0), "r"(a1), "r"(a2), "r"(a3), "r"(b0), "r"(b1));
}

// ---------------- gemm tile body (bf16x3, warp-mma) --------------------------
// Computes y rows [tile*128, tile*128+128) = x @ [W1_l | W1_r].
// 256 threads = 8 warps (2x4), warp tile 64x32 = 4x4 m16n8k16 sub-tiles, kb=32.
__device__ __forceinline__ void gemm_tile(const float* __restrict__ x,
                                          const float* __restrict__ Wl,
                                          const float* __restrict__ Wr,
                                          int n, int tile) {
    __shared__ unsigned xh[128][20], xlo[128][20];  // row-major x, 16 k-pairs + pad
    __shared__ unsigned wh[16][136], wlo[16][136];  // k-pair major W
    int tid = threadIdx.x;
    int lane = tid & 31;
    int wid = tid >> 5;
    int warp_m = wid >> 2;
    int warp_n = wid & 3;
    int gid = lane >> 2;
    int tig = lane & 3;
    int row0 = tile * 128;

    float c[4][4][4];
#pragma unroll
    for (int i = 0; i < 4; i++)
#pragma unroll
        for (int j = 0; j < 4; j++)
#pragma unroll
            for (int q = 0; q < 4; q++) c[i][j][q] = 0.0f;

    for (int kb = 0; kb < 128; kb += 32) {
        // x tile: 128 rows x 32 k = 1024 float4, 4 per thread; split+pack pairs
#pragma unroll
        for (int it = 0; it < 4; it++) {
            int i = tid + it * 256;
            int r = i >> 3, c4 = i & 7;
            int gr = row0 + r;
            float4 v = make_float4(0.f, 0.f, 0.f, 0.f);
            if (gr < n) v = *(const float4*)(x + (size_t)gr * 128 + kb + c4 * 4);
            unsigned short hx, lx, hy, ly, hz, lz, hw, lw;
            bsplit(v.x, hx, lx); bsplit(v.y, hy, ly);
            bsplit(v.z, hz, lz); bsplit(v.w, hw, lw);
            xh[r][c4 * 2 + 0] = pk(hx, hy);
            xlo[r][c4 * 2 + 0] = pk(lx, ly);
            xh[r][c4 * 2 + 1] = pk(hz, hw);
            xlo[r][c4 * 2 + 1] = pk(lz, lw);
        }
        // W tile: 32 k x 128 n; pack pairs along k. 512 pair-groups, 2/thread.
#pragma unroll
        for (int it = 0; it < 2; it++) {
            int i = tid + it * 256;
            int k2 = i >> 5, c4 = i & 31;
            int ka = kb + 2 * k2;
            float4 va, vb;
            if (c4 < 16) {
                va = *(const float4*)(Wl + ka * 64 + c4 * 4);
                vb = *(const float4*)(Wl + (ka + 1) * 64 + c4 * 4);
            } else {
                va = *(const float4*)(Wr + ka * 64 + (c4 - 16) * 4);
                vb = *(const float4*)(Wr + (ka + 1) * 64 + (c4 - 16) * 4);
            }
            float fa[4] = {va.x, va.y, va.z, va.w};
            float fb[4] = {vb.x, vb.y, vb.z, vb.w};
#pragma unroll
            for (int q = 0; q < 4; q++) {
                unsigned short ha, la, hb, lb;
                bsplit(fa[q], ha, la);
                bsplit(fb[q], hb, lb);
                wh[k2][c4 * 4 + q] = pk(ha, hb);
                wlo[k2][c4 * 4 + q] = pk(la, lb);
            }
        }
        __syncthreads();

#pragma unroll
        for (int ks = 0; ks < 2; ks++) {
            int k0p = ks * 8;
            unsigned bh[4][2], bl[4][2];
#pragma unroll
            for (int j = 0; j < 4; j++) {
                int col = warp_n * 32 + j * 8 + gid;
                bh[j][0] = wh[k0p + tig][col];
                bh[j][1] = wh[k0p + tig + 4][col];
                bl[j][0] = wlo[k0p + tig][col];
                bl[j][1] = wlo[k0p + tig + 4][col];
            }
#pragma unroll
            for (int i = 0; i < 4; i++) {
                int ar = warp_m * 64 + i * 16 + gid;
                unsigned ah[4], al[4];
                ah[0] = xh[ar][k0p + tig];
                ah[1] = xh[ar + 8][k0p + tig];
                ah[2] = xh[ar][k0p + tig + 4];
                ah[3] = xh[ar + 8][k0p + tig + 4];
                al[0] = xlo[ar][k0p + tig];
                al[1] = xlo[ar + 8][k0p + tig];
                al[2] = xlo[ar][k0p + tig + 4];
                al[3] = xlo[ar + 8][k0p + tig + 4];
#pragma unroll
                for (int j = 0; j < 4; j++) {
                    mma_bf16(c[i][j], ah[0], ah[1], ah[2], ah[3], bl[j][0], bl[j][1]);
                    mma_bf16(c[i][j], al[0], al[1], al[2], al[3], bh[j][0], bh[j][1]);
                    mma_bf16(c[i][j], ah[0], ah[1], ah[2], ah[3], bh[j][0], bh[j][1]);
                }
            }
        }
        __syncthreads();
    }

#pragma unroll
    for (int i = 0; i < 4; i++) {
        int r0 = row0 + warp_m * 64 + i * 16 + gid;
#pragma unroll
        for (int j = 0; j < 4; j++) {
            int col = warp_n * 32 + j * 8 + tig * 2;
            if (r0 < n)
                *(float2*)(g_y + (size_t)r0 * 128 + col) = make_float2(c[i][j][0], c[i][j][1]);
            if (r0 + 8 < n)
                *(float2*)(g_y + (size_t)(r0 + 8) * 128 + col) = make_float2(c[i][j][2], c[i][j][3]);
        }
    }
}

// ---------------- fused launch 1: gemm tiles [0, gb) || histogram -----------
__global__ void __launch_bounds__(256) gemm_hist_kernel(const float* __restrict__ x,
                                                        const float* __restrict__ Wl,
                                                        const float* __restrict__ Wr,
                                                        int n,
                                                        const int* __restrict__ dst,
                                                        int e, int gb, int auxb) {
    if ((int)blockIdx.x < gb) {
        gemm_tile(x, Wl, Wr, n, blockIdx.x);
    } else {
        int t0 = ((int)blockIdx.x - gb) * 256 + threadIdx.x;
        int stride = auxb * 256;
        for (int i = t0; i < e; i += stride) atomicAdd(&g_deg[dst[i]], 1);
    }
}

// ---------------- fused launch 2: gemm tiles [gb, nt) || scatter -------------
__global__ void __launch_bounds__(256) gemm_scatter_kernel(const float* __restrict__ x,
                                                           const float* __restrict__ Wl,
                                                           const float* __restrict__ Wr,
                                                           int n,
                                                           const int* __restrict__ src,
                                                           const int* __restrict__ dst,
                                                           int e, int gb, int auxb) {
    if ((int)blockIdx.x < gb) {
        gemm_tile(x, Wl, Wr, n, gb + (int)blockIdx.x);  // second half of tiles
    } else {
        int t0 = ((int)blockIdx.x - gb) * 256 + threadIdx.x;
        int stride = auxb * 256;
        for (int i = t0; i < e; i += stride) {
            int d = dst[i];
            int p = atomicAdd(&g_cursor[d], 1);
            g_srclist[p] = src[i];
        }
    }
}

// ---------------- CSR scan stages --------------------------------------------
// per-block exclusive scan over 256 elements
__global__ void __launch_bounds__(256) scan_block_kernel(int n) {
    __shared__ int s[256];
    int i = blockIdx.x * 256 + threadIdx.x;
    int v = (i < n) ? g_deg[i] : 0;
    s[threadIdx.x] = v;
    __syncthreads();
#pragma unroll
    for (int off = 1; off < 256; off <<= 1) {
        int t = 0;
        if ((int)threadIdx.x >= off) t = s[threadIdx.x - off];
        __syncthreads();
        if ((int)threadIdx.x >= off) s[threadIdx.x] += t;
        __syncthreads();
    }
    if (i < n) g_rowstart[i] = s[threadIdx.x] - v;  // exclusive within block
    if (threadIdx.x == 255) g_blocksums[blockIdx.x] = s[255];
}

// add_offsets with inlined block-sum prefix
__global__ void __launch_bounds__(256) add_offsets_kernel(int n, int e) {
    __shared__ int red[256];
    int b = blockIdx.x;
    int t = threadIdx.x;
    int part = 0;
    for (int i = t; i < b; i += 256) part += g_blocksums[i];
    red[t] = part;
    __syncthreads();
#pragma unroll
    for (int off = 128; off > 0; off >>= 1) {
        if (t < off) red[t] += red[t + off];
        __syncthreads();
    }
    int base = red[0];
    int i = b * 256 + t;
    if (i < n) {
        int r = g_rowstart[i] + base;
        g_rowstart[i] = r;
        g_cursor[i]   = r;
    }
    if (b == 0 && t == 0) g_rowstart[n] = e;
}

// ---------------- layer 1 combine + z (R10-proven, at L2 floor) --------------
__global__ void __launch_bounds__(256) layer1_kernel(const float* __restrict__ b1,
                                                     const float* __restrict__ mask,
                                                     const float* __restrict__ W2l,
                                                     int n) {
    __shared__ __align__(16) float w2[512];
    __shared__ float b1s[64];
    for (int i = threadIdx.x; i < 512; i += 256) w2[i] = W2l[i];
    if (threadIdx.x < 64) b1s[threadIdx.x] = b1[threadIdx.x];
    __syncthreads();

    int node = blockIdx.x * 8 + (threadIdx.x >> 5);
    int lane = threadIdx.x & 31;
    int d = lane * 2;
    if (node >= n) return;
    int s = g_rowstart[node];
    int epos = g_rowstart[node + 1];
    float2 a0 = make_float2(0.f, 0.f), a1 = make_float2(0.f, 0.f);
    float2 a2 = make_float2(0.f, 0.f), a3 = make_float2(0.f, 0.f);
    int e = s;
    for (; e + 4 <= epos; e += 4) {
        int s0 = g_srclist[e], s1 = g_srclist[e + 1];
        int s2 = g_srclist[e + 2], s3 = g_srclist[e + 3];
        float2 v0 = *(const float2*)(g_y + (size_t)s0 * 128 + d);
        float2 v1 = *(const float2*)(g_y + (size_t)s1 * 128 + d);
        float2 v2 = *(const float2*)(g_y + (size_t)s2 * 128 + d);
        float2 v3 = *(const float2*)(g_y + (size_t)s3 * 128 + d);
        a0.x += v0.x; a0.y += v0.y;
        a1.x += v1.x; a1.y += v1.y;
        a2.x += v2.x; a2.y += v2.y;
        a3.x += v3.x; a3.y += v3.y;
    }
    for (; e < epos; e++) {
        float2 v = *(const float2*)(g_y + (size_t)g_srclist[e] * 128 + d);
        a0.x += v.x; a0.y += v.y;
    }
    float sx = (a0.x + a1.x) + (a2.x + a3.x);
    float sy = (a0.y + a1.y) + (a2.y + a3.y);
    float inv = 1.0f / fmaxf((float)(epos - s), 1.0f);
    float2 yr = *(const float2*)(g_y + (size_t)node * 128 + 64 + d);
    float hx = sx * inv + yr.x + b1s[d];
    float hy = sy * inv + yr.y + b1s[d + 1];
    hx = fmaxf(hx, 0.0f);
    hy = fmaxf(hy, 0.0f);
    float2 mk = *(const float2*)(mask + (size_t)node * 64 + d);
    hx = (mk.x > 0.5f) ? hx * 2.0f : 0.0f;
    hy = (mk.y > 0.5f) ? hy * 2.0f : 0.0f;
    *(float2*)(g_h + (size_t)node * 64 + d) = make_float2(hx, hy);

    // z = h @ W2_l : per-lane partials over its 2 dims, butterfly across warp
    float zacc[8];
#pragma unroll
    for (int j = 0; j < 8; j++)
        zacc[j] = hx * w2[d * 8 + j] + hy * w2[(d + 1) * 8 + j];
#pragma unroll
    for (int off = 16; off > 0; off >>= 1)
#pragma unroll
        for (int j = 0; j < 8; j++)
            zacc[j] += __shfl_xor_sync(0xffffffffu, zacc[j], off);
    if (lane == 0) {
        float4* zp = (float4*)(g_z + (size_t)node * 8);
        zp[0] = make_float4(zacc[0], zacc[1], zacc[2], zacc[3]);
        zp[1] = make_float4(zacc[4], zacc[5], zacc[6], zacc[7]);
    }
}

// ---------------- output: out[b] = agg2(idx[b])/deg + h[idx[b]]@W2_r + b2 ---
__global__ void __launch_bounds__(256) out_kernel(const int* __restrict__ idx,
                                                  const float* __restrict__ W2r,
                                                  const float* __restrict__ b2,
                                                  float* __restrict__ out,
                                                  int bcnt) {
    __shared__ __align__(16) float w[512];
    __shared__ float bb[8];
    for (int i = threadIdx.x; i < 512; i += 256) w[i] = W2r[i];
    if (threadIdx.x < 8) bb[threadIdx.x] = b2[threadIdx.x];
    __syncthreads();
    int b = blockIdx.x * 32 + (threadIdx.x >> 3);
    int j = threadIdx.x & 7;
    if (b >= bcnt) return;
    int node = idx[b];
    int s = g_rowstart[node];
    int epos = g_rowstart[node + 1];
    float a0 = 0.f, a1 = 0.f, a2 = 0.f, a3 = 0.f;
    int e = s;
    for (; e + 4 <= epos; e += 4) {
        int s0 = g_srclist[e], s1 = g_srclist[e + 1];
        int s2 = g_srclist[e + 2], s3 = g_srclist[e + 3];
        a0 += g_z[(size_t)s0 * 8 + j];
        a1 += g_z[(size_t)s1 * 8 + j];
        a2 += g_z[(size_t)s2 * 8 + j];
        a3 += g_z[(size_t)s3 * 8 + j];
    }
    for (; e < epos; e++) a0 += g_z[(size_t)g_srclist[e] * 8 + j];
    float acc = ((a0 + a1) + (a2 + a3)) / fmaxf((float)(epos - s), 1.0f);
    const float* hr = g_h + (size_t)node * 64;
    float dot = 0.f;
#pragma unroll
    for (int k = 0; k < 64; k++) dot += hr[k] * w[k * 8 + j];
    out[(size_t)b * 8 + j] = acc + dot + bb[j];
}

// ---------------- launch -----------------------------------------------------
extern "C" void kernel_launch(void* const* d_in, const int* in_sizes, int n_in,
                              void* d_out, int out_size) {
    const float* x    = (const float*)d_in[0];
    const int*   edge = (const int*)d_in[1];   // int32 (JAX x64 disabled)
    const int*   idx  = (const int*)d_in[2];   // int32
    const float* mask = (const float*)d_in[3];
    const float* W1l  = (const float*)d_in[4];
    const float* W1r  = (const float*)d_in[5];
    const float* b1   = (const float*)d_in[6];
    const float* W2l  = (const float*)d_in[7];
    const float* W2r  = (const float*)d_in[8];
    const float* b2   = (const float*)d_in[9];
    float* out = (float*)d_out;

    int n = in_sizes[0] / 128;
    int e = in_sizes[1] / 2;
    int bcnt = in_sizes[2];
    const int* src = edge;
    const int* dst = edge + e;

    int nb = (n + 255) / 256;            // 391 scan blocks
    int ntiles = (n + 127) / 128;        // 782 gemm tiles
    int gb1 = (ntiles + 1) / 2;          // first-half tiles (391)
    int gb2 = ntiles - gb1;              // second-half tiles (391)
    int auxb = 1024;                     // aux (hist/scatter) blocks per fused grid

    void* deg_ptr = 0;
    cudaGetSymbolAddress(&deg_ptr, g_deg);

    cudaMemsetAsync(deg_ptr, 0, n * sizeof(int), 0);
    // L2: first half of gemm tiles co-scheduled with histogram
    gemm_hist_kernel<<<gb1 + auxb, 256>>>(x, W1l, W1r, n, dst, e, gb1, auxb);
    // L3/L4: prefix-sum stages (launch boundaries give the needed grid syncs)
    scan_block_kernel<<<nb, 256>>>(n);
    add_offsets_kernel<<<nb, 256>>>(n, e);
    // L5: second half of gemm tiles co-scheduled with scatter
    gemm_scatter_kernel<<<gb2 + auxb, 256>>>(x, W1l, W1r, n, src, dst, e, gb2, auxb);
    // L6/L7
    layer1_kernel<<<(n + 7) / 8, 256>>>(b1, mask, W2l, n);
    out_kernel<<<(bcnt + 31) / 32, 256>>>(idx, W2r, b2, out, bcnt);
}